// round 9
// baseline (speedup 1.0000x reference)
#include <cuda_runtime.h>
#include <cuda_bf16.h>
#include <cstdint>

#define D_MODEL  256
#define D_HIDDEN 1024
#define TM       64          // tokens per CTA
#define HSd      132         // Hs row stride (floats)

// ---- SMEM byte offsets ----
#define XF_OFF     0                         // X A-frag: 64KB
#define HS_OFF     65536                     // Hs: 64*132*4 = 33792
#define RING_OFF   99328                     // 3 x 32KB weight tile ring
#define B1_OFF     197632                    // 4KB
#define B2_OFF     201728                    // 1KB
#define SMEM_TOTAL 202752

// Pre-masked, tf32-rounded weights in MMA fragment-pair layout (see prep_weights).
__device__ float g_w1f[D_HIDDEN * D_MODEL];
__device__ float g_w2f[D_HIDDEN * D_MODEL];

// ======================= helpers =======================
__device__ __forceinline__ uint32_t tf32bits(float x) {
    uint32_t u;
    asm("cvt.rna.tf32.f32 %0, %1;" : "=r"(u) : "f"(x));
    return u;
}
__device__ __forceinline__ float tf32r(float x) { return __uint_as_float(tf32bits(x)); }

__device__ __forceinline__ uint32_t smem_u32(const void* p) {
    uint32_t a;
    asm("{ .reg .u64 t; cvta.to.shared.u64 t, %1; cvt.u32.u64 %0, t; }" : "=r"(a) : "l"(p));
    return a;
}

__device__ __forceinline__ void mma_t(float c[4], const float4& A, float b0, float b1) {
    asm volatile(
        "mma.sync.aligned.m16n8k8.row.col.f32.tf32.tf32.f32 "
        "{%0,%1,%2,%3}, {%4,%5,%6,%7}, {%8,%9}, {%0,%1,%2,%3};\n"
        : "+f"(c[0]), "+f"(c[1]), "+f"(c[2]), "+f"(c[3])
        : "r"(__float_as_uint(A.x)), "r"(__float_as_uint(A.y)),
          "r"(__float_as_uint(A.z)), "r"(__float_as_uint(A.w)),
          "r"(__float_as_uint(b0)), "r"(__float_as_uint(b1)));
}

#define CP_COMMIT() asm volatile("cp.async.commit_group;" ::: "memory")
#define CP_WAIT0()  asm volatile("cp.async.wait_group 0;" ::: "memory")
#define CP_WAIT1()  asm volatile("cp.async.wait_group 1;" ::: "memory")

// Issue one 32KB weight tile (t in 0..63) into ring slot `slot`. 256 threads.
__device__ __forceinline__ void issue_tile(int t, int slot, int tid, uint32_t ring) {
    const float* src = ((t & 7) < 4)
        ? (g_w1f + (((t >> 3) * 4 + (t & 7)) << 13))
        : (g_w2f + (((t >> 3) * 4 + ((t & 7) - 4)) << 13));
    uint64_t gs = __cvta_generic_to_global(src) + (uint64_t)tid * 16;
    uint32_t ds = ring + slot * 32768 + tid * 16;
    #pragma unroll
    for (int i = 0; i < 8; i++)
        asm volatile("cp.async.cg.shared.global [%0], [%1], 16;"
                     :: "r"(ds + i * 4096), "l"(gs + i * 4096));
    CP_COMMIT();
}

// ============ weight prep: mask + tf32 round + fragment-pair pack ============
__global__ void prep_weights(const float* __restrict__ w1,
                             const float* __restrict__ w2,
                             const int* __restrict__ mask) {
    int idx = blockIdx.x * blockDim.x + threadIdx.x;
    if (idx >= D_HIDDEN * D_MODEL) return;
    int h = idx >> 8;
    int d = idx & 255;
    float m = (mask[idx] != 0) ? 1.0f : 0.0f;

    // ---- W1 frag: value w1[h][d]*m at MMA-B position (n-row = h, k = d) ----
    {
        float v = tf32r(w1[idx] * m);
        int hc = h >> 7, hin = h & 127;
        int jp = hin >> 4, par = (hin >> 3) & 1, g = hin & 7;
        int kt = d >> 6, din = d & 63;
        int k8 = din >> 3, q = din & 3, half = (din >> 2) & 1;
        g_w1f[(((hc * 4 + kt) << 13)) +
              ((jp * 8 + k8) * 32 + g * 4 + q) * 4 + par * 2 + half] = v;
    }
    // ---- W2 frag: value w2[d][h]*m at MMA-B position (n-row = d, k = h) ----
    {
        float v = tf32r(w2[(size_t)d * D_HIDDEN + h] * m);
        int hc = h >> 7, hin = h & 127;
        int kt2 = hin >> 5, kin = hin & 31;
        int k8 = kin >> 3, q = kin & 3, half = (kin >> 2) & 1;
        int jp = d >> 4, par = (d >> 3) & 1, g = d & 7;
        g_w2f[(((hc * 4 + kt2) << 13)) +
              ((jp * 4 + k8) * 32 + g * 4 + q) * 4 + par * 2 + half] = v;
    }
}

// ======================= fused MLP =======================
__global__ __launch_bounds__(256, 1)
void ffd_mma(const float* __restrict__ x,
             const float* __restrict__ b1,
             const float* __restrict__ b2,
             float* __restrict__ out,
             int n_tokens) {
    extern __shared__ char smem[];
    float* XsF = (float*)(smem + XF_OFF);
    float* Hs  = (float*)(smem + HS_OFF);
    float* b1s = (float*)(smem + B1_OFF);
    float* b2s = (float*)(smem + B2_OFF);
    const uint32_t ring = smem_u32(smem + RING_OFF);

    const int tid  = threadIdx.x;
    const int warp = tid >> 5;
    const int lane = tid & 31;
    const int g    = lane >> 2;
    const int q    = lane & 3;
    const int wm   = warp & 1;     // m 32-row block (0..1)
    const int wq   = warp >> 1;    // n quarter (0..3)
    const int mt   = blockIdx.x * TM;

    // Prefetch weight tiles 0 and 1 (overlap X fill)
    issue_tile(0, 0, tid, ring);
    issue_tile(1, 1, tid, ring);

    // ---- X tile -> A-fragment layout (tf32-rounded) ----
    #pragma unroll
    for (int i = 0; i < 16; i++) {
        int lin = tid + i * 256;          // 4096 float4 total
        int row = lin >> 6, c4 = lin & 63;
        int tok = mt + row;
        float4 v = make_float4(0.f, 0.f, 0.f, 0.f);
        if (tok < n_tokens)
            v = *reinterpret_cast<const float4*>(x + (size_t)tok * D_MODEL + c4 * 4);
        int k8 = c4 >> 1;
        int slot = (c4 & 1) * 2 + ((row >> 3) & 1);
        int base = ((row >> 4) * 32 + k8) * 32 + (row & 7) * 4;
        XsF[(base + 0) * 4 + slot] = tf32r(v.x);
        XsF[(base + 1) * 4 + slot] = tf32r(v.y);
        XsF[(base + 2) * 4 + slot] = tf32r(v.z);
        XsF[(base + 3) * 4 + slot] = tf32r(v.w);
    }
    #pragma unroll
    for (int i = tid; i < D_HIDDEN; i += 256) b1s[i] = b1[i];
    b2s[tid] = b2[tid];
    __syncthreads();

    float yacc[2][8][4];
    #pragma unroll
    for (int a = 0; a < 2; a++)
        #pragma unroll
        for (int j = 0; j < 8; j++)
            #pragma unroll
            for (int r = 0; r < 4; r++) yacc[a][j][r] = 0.f;

    const float4* XsF4 = (const float4*)XsF;
    int t = 0;
    int slot = 0;                       // t % 3

    for (int hc = 0; hc < 8; hc++) {
        float hacc[2][4][4];
        #pragma unroll
        for (int a = 0; a < 2; a++)
            #pragma unroll
            for (int j = 0; j < 4; j++)
                #pragma unroll
                for (int r = 0; r < 4; r++) hacc[a][j][r] = 0.f;

        // ======== GEMM1: H[64,128] += X[64,256] @ W1c^T ========
        // warp computes rows [wm*32, +32), hidden cols [wq*32, +32)
        for (int kt = 0; kt < 4; kt++) {
            if (t < 62) CP_WAIT1(); else CP_WAIT0();   // tile t landed
            __syncthreads();                            // slot reuse safe
            if (t + 2 < 64) {
                int s2 = slot + 2; if (s2 >= 3) s2 -= 3;
                issue_tile(t + 2, s2, tid, ring);
            }
            const float4* Bt = (const float4*)(smem + RING_OFF + slot * 32768);

            #pragma unroll
            for (int k8l = 0; k8l < 8; k8l++) {
                const int k8 = kt * 8 + k8l;
                float4 A0 = XsF4[((wm * 2 + 0) * 32 + k8) * 32 + lane];
                float4 A1 = XsF4[((wm * 2 + 1) * 32 + k8) * 32 + lane];
                #pragma unroll
                for (int jpl = 0; jpl < 2; jpl++) {
                    int jp = wq * 2 + jpl;
                    float4 B2 = Bt[(jp * 8 + k8l) * 32 + lane];
                    mma_t(hacc[0][2 * jpl],     A0, B2.x, B2.y);
                    mma_t(hacc[0][2 * jpl + 1], A0, B2.z, B2.w);
                    mma_t(hacc[1][2 * jpl],     A1, B2.x, B2.y);
                    mma_t(hacc[1][2 * jpl + 1], A1, B2.z, B2.w);
                }
            }
            t++; slot++; if (slot == 3) slot = 0;
        }

        // ---- bias + relu -> Hs (row-major, tf32-rounded) ----
        #pragma unroll
        for (int mt2 = 0; mt2 < 2; mt2++) {
            int r0 = wm * 32 + mt2 * 16 + g;
            #pragma unroll
            for (int j = 0; j < 4; j++) {
                int hl = wq * 32 + 8 * j + 2 * q;
                float bb0 = b1s[hc * 128 + hl];
                float bb1 = b1s[hc * 128 + hl + 1];
                float2 v0, v1;
                v0.x = tf32r(fmaxf(hacc[mt2][j][0] + bb0, 0.f));
                v0.y = tf32r(fmaxf(hacc[mt2][j][1] + bb1, 0.f));
                v1.x = tf32r(fmaxf(hacc[mt2][j][2] + bb0, 0.f));
                v1.y = tf32r(fmaxf(hacc[mt2][j][3] + bb1, 0.f));
                *reinterpret_cast<float2*>(&Hs[r0 * HSd + hl]) = v0;
                *reinterpret_cast<float2*>(&Hs[(r0 + 8) * HSd + hl]) = v1;
            }
        }

        // ======== GEMM2: Y[64,256] += relu(H)[64,128] @ W2c ========
        // warp computes rows [wm*32, +32), out cols [wq*64, +64)
        for (int kt2 = 0; kt2 < 4; kt2++) {
            if (t < 62) CP_WAIT1(); else CP_WAIT0();
            __syncthreads();                 // Hs visible + slot reuse safe
            if (t + 2 < 64) {
                int s2 = slot + 2; if (s2 >= 3) s2 -= 3;
                issue_tile(t + 2, s2, tid, ring);
            }
            const float4* Bt = (const float4*)(smem + RING_OFF + slot * 32768);

            #pragma unroll
            for (int k8l = 0; k8l < 4; k8l++) {
                const int kk = kt2 * 32 + k8l * 8;
                float4 a[2];
                #pragma unroll
                for (int mt2 = 0; mt2 < 2; mt2++) {
                    int r0 = wm * 32 + mt2 * 16 + g;
                    a[mt2].x = Hs[r0 * HSd + kk + q];
                    a[mt2].z = Hs[r0 * HSd + kk + q + 4];
                    a[mt2].y = Hs[(r0 + 8) * HSd + kk + q];
                    a[mt2].w = Hs[(r0 + 8) * HSd + kk + q + 4];
                }
                #pragma unroll
                for (int jpl = 0; jpl < 4; jpl++) {
                    int jp = wq * 4 + jpl;
                    float4 B2 = Bt[(jp * 4 + k8l) * 32 + lane];
                    mma_t(yacc[0][2 * jpl],     a[0], B2.x, B2.y);
                    mma_t(yacc[0][2 * jpl + 1], a[0], B2.z, B2.w);
                    mma_t(yacc[1][2 * jpl],     a[1], B2.x, B2.y);
                    mma_t(yacc[1][2 * jpl + 1], a[1], B2.z, B2.w);
                }
            }
            t++; slot++; if (slot == 3) slot = 0;
        }
    }

    // ---- epilogue: + b2, write out ----
    #pragma unroll
    for (int mt2 = 0; mt2 < 2; mt2++) {
        int r0 = wm * 32 + mt2 * 16 + g;
        int tok0 = mt + r0;
        int tok1 = tok0 + 8;
        #pragma unroll
        for (int j = 0; j < 8; j++) {
            int d = wq * 64 + 8 * j + 2 * q;
            float bb0 = b2s[d];
            float bb1 = b2s[d + 1];
            if (tok0 < n_tokens) {
                float2 v = make_float2(yacc[mt2][j][0] + bb0, yacc[mt2][j][1] + bb1);
                *reinterpret_cast<float2*>(out + (size_t)tok0 * D_MODEL + d) = v;
            }
            if (tok1 < n_tokens) {
                float2 v = make_float2(yacc[mt2][j][2] + bb0, yacc[mt2][j][3] + bb1);
                *reinterpret_cast<float2*>(out + (size_t)tok1 * D_MODEL + d) = v;
            }
        }
    }
}

extern "C" void kernel_launch(void* const* d_in, const int* in_sizes, int n_in,
                              void* d_out, int out_size) {
    // inputs (metadata order): x, w1, b1, w2, b2, mask
    const float* x    = (const float*)d_in[0];
    const float* w1   = (const float*)d_in[1];
    const float* b1   = (const float*)d_in[2];
    const float* w2   = (const float*)d_in[3];
    const float* b2   = (const float*)d_in[4];
    const int*   mask = (const int*)d_in[5];
    float* out = (float*)d_out;

    const int n_tokens = in_sizes[0] / D_MODEL;

    prep_weights<<<(D_HIDDEN * D_MODEL + 255) / 256, 256>>>(w1, w2, mask);

    cudaFuncSetAttribute(ffd_mma, cudaFuncAttributeMaxDynamicSharedMemorySize, SMEM_TOTAL);
    const int grid = (n_tokens + TM - 1) / TM;
    ffd_mma<<<grid, 256, SMEM_TOTAL>>>(x, b1, b2, out, n_tokens);
}

// round 10
// speedup vs baseline: 1.3464x; 1.3464x over previous
#include <cuda_runtime.h>
#include <cuda_bf16.h>
#include <cstdint>

#define D_MODEL  256
#define D_HIDDEN 1024
#define TM       64          // tokens per CTA
#define HS2      260         // Hs row stride (floats): 260 % 32 = 4 -> conflict-free frag loads

// ---- SMEM byte offsets ----
#define XF_OFF     0                         // X A-frag: 64KB
#define HS_OFF     65536                     // Hs: 64*260*4 = 66560
#define B1_OFF     132096                    // 4KB
#define B2_OFF     136192                    // 1KB
#define SMEM_TOTAL 137216

// Pre-masked, tf32-rounded weights in MMA fragment-pair layout (see prep_weights).
// W1 tiles (hc,kt): 32KB each; W2 tiles (hc,kt2): 32KB each. Read via LDG (L2-resident).
__device__ float g_w1f[D_HIDDEN * D_MODEL];
__device__ float g_w2f[D_HIDDEN * D_MODEL];

// ======================= helpers =======================
__device__ __forceinline__ uint32_t tf32bits(float x) {
    uint32_t u;
    asm("cvt.rna.tf32.f32 %0, %1;" : "=r"(u) : "f"(x));
    return u;
}
__device__ __forceinline__ float tf32r(float x) { return __uint_as_float(tf32bits(x)); }

__device__ __forceinline__ void mma_t(float c[4], const float4& A, float b0, float b1) {
    asm volatile(
        "mma.sync.aligned.m16n8k8.row.col.f32.tf32.tf32.f32 "
        "{%0,%1,%2,%3}, {%4,%5,%6,%7}, {%8,%9}, {%0,%1,%2,%3};\n"
        : "+f"(c[0]), "+f"(c[1]), "+f"(c[2]), "+f"(c[3])
        : "r"(__float_as_uint(A.x)), "r"(__float_as_uint(A.y)),
          "r"(__float_as_uint(A.z)), "r"(__float_as_uint(A.w)),
          "r"(__float_as_uint(b0)), "r"(__float_as_uint(b1)));
}

// ============ weight prep: mask + tf32 round + fragment-pair pack ============
// (unchanged from the passing R7/R8 kernels — layout verified)
__global__ void prep_weights(const float* __restrict__ w1,
                             const float* __restrict__ w2,
                             const int* __restrict__ mask) {
    int idx = blockIdx.x * blockDim.x + threadIdx.x;
    if (idx >= D_HIDDEN * D_MODEL) return;
    int h = idx >> 8;
    int d = idx & 255;
    float m = (mask[idx] != 0) ? 1.0f : 0.0f;

    // ---- W1 frag: value w1[h][d]*m at MMA-B position (n-row = h, k = d) ----
    {
        float v = tf32r(w1[idx] * m);
        int hc = h >> 7, hin = h & 127;
        int jp = hin >> 4, par = (hin >> 3) & 1, g = hin & 7;
        int kt = d >> 6, din = d & 63;
        int k8 = din >> 3, q = din & 3, half = (din >> 2) & 1;
        g_w1f[(((hc * 4 + kt) << 13)) +
              ((jp * 8 + k8) * 32 + g * 4 + q) * 4 + par * 2 + half] = v;
    }
    // ---- W2 frag: value w2[d][h]*m at MMA-B position (n-row = d, k = h) ----
    {
        float v = tf32r(w2[(size_t)d * D_HIDDEN + h] * m);
        int hc = h >> 7, hin = h & 127;
        int kt2 = hin >> 5, kin = hin & 31;
        int k8 = kin >> 3, q = kin & 3, half = (kin >> 2) & 1;
        int jp = d >> 4, par = (d >> 3) & 1, g = d & 7;
        g_w2f[(((hc * 4 + kt2) << 13)) +
              ((jp * 4 + k8) * 32 + g * 4 + q) * 4 + par * 2 + half] = v;
    }
}

// ======================= fused MLP (weights via LDG from L2) =======================
__global__ __launch_bounds__(256, 1)
void ffd_mma(const float* __restrict__ x,
             const float* __restrict__ b1,
             const float* __restrict__ b2,
             float* __restrict__ out,
             int n_tokens) {
    extern __shared__ char smem[];
    float* XsF = (float*)(smem + XF_OFF);
    float* Hs  = (float*)(smem + HS_OFF);
    float* b1s = (float*)(smem + B1_OFF);
    float* b2s = (float*)(smem + B2_OFF);

    const int tid   = threadIdx.x;
    const int warp  = tid >> 5;    // 0..7
    const int lane  = tid & 31;
    const int g     = lane >> 2;
    const int q     = lane & 3;
    const int hcoff = warp >> 2;   // 0..1: which old 128-hidden block within the 256-pass
    const int wq4   = warp & 3;    // 0..3: 32-col stripe within the 128 block
    const int mt    = blockIdx.x * TM;

    // ---- X tile -> A-fragment layout (tf32-rounded), verified in R8 ----
    #pragma unroll
    for (int i = 0; i < 16; i++) {
        int lin = tid + i * 256;          // 4096 float4 total
        int row = lin >> 6, c4 = lin & 63;
        int tok = mt + row;
        float4 v = make_float4(0.f, 0.f, 0.f, 0.f);
        if (tok < n_tokens)
            v = *reinterpret_cast<const float4*>(x + (size_t)tok * D_MODEL + c4 * 4);
        int k8 = c4 >> 1;
        int slot = (c4 & 1) * 2 + ((row >> 3) & 1);
        int base = ((row >> 4) * 32 + k8) * 32 + (row & 7) * 4;
        XsF[(base + 0) * 4 + slot] = tf32r(v.x);
        XsF[(base + 1) * 4 + slot] = tf32r(v.y);
        XsF[(base + 2) * 4 + slot] = tf32r(v.z);
        XsF[(base + 3) * 4 + slot] = tf32r(v.w);
    }
    #pragma unroll
    for (int i = tid; i < D_HIDDEN; i += 256) b1s[i] = b1[i];
    b2s[tid] = b2[tid];
    __syncthreads();

    float yacc[4][4][4];
    #pragma unroll
    for (int m = 0; m < 4; m++)
        #pragma unroll
        for (int j = 0; j < 4; j++)
            #pragma unroll
            for (int r = 0; r < 4; r++) yacc[m][j][r] = 0.f;

    const float4* XsF4 = (const float4*)XsF;

    for (int p = 0; p < 4; p++) {          // pass over 256 hidden units
        float hacc[4][4][4];
        #pragma unroll
        for (int m = 0; m < 4; m++)
            #pragma unroll
            for (int j = 0; j < 4; j++)
                #pragma unroll
                for (int r = 0; r < 4; r++) hacc[m][j][r] = 0.f;

        // ======== GEMM1: H[64,256] = X[64,256] @ W1p^T ========
        // warp computes all 64 rows x hidden cols [hcoff*128 + wq4*32, +32)
        const float4* w1t = (const float4*)g_w1f + ((size_t)((p * 2 + hcoff) * 4) << 11);
        #pragma unroll
        for (int kt = 0; kt < 4; kt++) {
            const float4* wt = w1t + ((size_t)kt << 11);
            #pragma unroll
            for (int k8l = 0; k8l < 8; k8l++) {
                const int k8 = kt * 8 + k8l;
                float4 B0 = __ldg(wt + ((wq4 * 2 + 0) * 8 + k8l) * 32 + lane);
                float4 B1v = __ldg(wt + ((wq4 * 2 + 1) * 8 + k8l) * 32 + lane);
                #pragma unroll
                for (int m = 0; m < 4; m++) {
                    float4 A = XsF4[(m * 32 + k8) * 32 + lane];
                    mma_t(hacc[m][0], A, B0.x, B0.y);
                    mma_t(hacc[m][1], A, B0.z, B0.w);
                    mma_t(hacc[m][2], A, B1v.x, B1v.y);
                    mma_t(hacc[m][3], A, B1v.z, B1v.w);
                }
            }
        }

        __syncthreads();   // previous pass GEMM2 done reading Hs (program order + this barrier)

        // ---- bias + relu -> Hs (row-major local cols 0..255, tf32-rounded) ----
        #pragma unroll
        for (int m = 0; m < 4; m++) {
            int r0 = m * 16 + g;
            #pragma unroll
            for (int j = 0; j < 4; j++) {
                int hl = hcoff * 128 + wq4 * 32 + (j >> 1) * 16 + (j & 1) * 8 + 2 * q;
                float bb0 = b1s[p * 256 + hl];
                float bb1 = b1s[p * 256 + hl + 1];
                float2 v0, v1;
                v0.x = tf32r(fmaxf(hacc[m][j][0] + bb0, 0.f));
                v0.y = tf32r(fmaxf(hacc[m][j][1] + bb1, 0.f));
                v1.x = tf32r(fmaxf(hacc[m][j][2] + bb0, 0.f));
                v1.y = tf32r(fmaxf(hacc[m][j][3] + bb1, 0.f));
                *reinterpret_cast<float2*>(&Hs[r0 * HS2 + hl]) = v0;
                *reinterpret_cast<float2*>(&Hs[(r0 + 8) * HS2 + hl]) = v1;
            }
        }
        __syncthreads();

        // ======== GEMM2: Y[64,256] += relu(H)[64,256] @ W2p ========
        // warp computes all 64 rows x out cols [warp*32, +32)
        #pragma unroll
        for (int t8 = 0; t8 < 8; t8++) {   // old subtile: hc = p*2 + (t8>>2), kt2 = t8&3
            const float4* wt2 = (const float4*)g_w2f +
                ((size_t)((p * 2 + (t8 >> 2)) * 4 + (t8 & 3)) << 11);
            #pragma unroll
            for (int k8 = 0; k8 < 4; k8++) {
                const int kc = (t8 * 4 + k8) * 8;     // local hidden col 0..255
                float4 B0 = __ldg(wt2 + ((warp * 2 + 0) * 4 + k8) * 32 + lane);
                float4 B1v = __ldg(wt2 + ((warp * 2 + 1) * 4 + k8) * 32 + lane);
                #pragma unroll
                for (int m = 0; m < 4; m++) {
                    int r0 = m * 16 + g;
                    float4 a;
                    a.x = Hs[r0 * HS2 + kc + q];
                    a.y = Hs[(r0 + 8) * HS2 + kc + q];
                    a.z = Hs[r0 * HS2 + kc + q + 4];
                    a.w = Hs[(r0 + 8) * HS2 + kc + q + 4];
                    mma_t(yacc[m][0], a, B0.x, B0.y);
                    mma_t(yacc[m][1], a, B0.z, B0.w);
                    mma_t(yacc[m][2], a, B1v.x, B1v.y);
                    mma_t(yacc[m][3], a, B1v.z, B1v.w);
                }
            }
        }
    }

    // ---- epilogue: + b2, write out ----
    #pragma unroll
    for (int m = 0; m < 4; m++) {
        int r0 = m * 16 + g;
        int tok0 = mt + r0;
        int tok1 = tok0 + 8;
        #pragma unroll
        for (int j = 0; j < 4; j++) {
            int d = warp * 32 + (j >> 1) * 16 + (j & 1) * 8 + 2 * q;
            float bb0 = b2s[d];
            float bb1 = b2s[d + 1];
            if (tok0 < n_tokens) {
                float2 v = make_float2(yacc[m][j][0] + bb0, yacc[m][j][1] + bb1);
                *reinterpret_cast<float2*>(out + (size_t)tok0 * D_MODEL + d) = v;
            }
            if (tok1 < n_tokens) {
                float2 v = make_float2(yacc[m][j][2] + bb0, yacc[m][j][3] + bb1);
                *reinterpret_cast<float2*>(out + (size_t)tok1 * D_MODEL + d) = v;
            }
        }
    }
}

extern "C" void kernel_launch(void* const* d_in, const int* in_sizes, int n_in,
                              void* d_out, int out_size) {
    // inputs (metadata order): x, w1, b1, w2, b2, mask
    const float* x    = (const float*)d_in[0];
    const float* w1   = (const float*)d_in[1];
    const float* b1   = (const float*)d_in[2];
    const float* w2   = (const float*)d_in[3];
    const float* b2   = (const float*)d_in[4];
    const int*   mask = (const int*)d_in[5];
    float* out = (float*)d_out;

    const int n_tokens = in_sizes[0] / D_MODEL;

    prep_weights<<<(D_HIDDEN * D_MODEL + 255) / 256, 256>>>(w1, w2, mask);

    cudaFuncSetAttribute(ffd_mma, cudaFuncAttributeMaxDynamicSharedMemorySize, SMEM_TOTAL);
    const int grid = (n_tokens + TM - 1) / TM;
    ffd_mma<<<grid, 256, SMEM_TOTAL>>>(x, b1, b2, out, n_tokens);
}

// round 13
// speedup vs baseline: 2.3797x; 1.7674x over previous
#include <cuda_runtime.h>
#include <cuda_fp16.h>
#include <cstdint>

#define D_MODEL  256
#define D_HIDDEN 1024
#define TM       64          // tokens per CTA
#define HS2h     264         // Hs row stride in halves: 528B % 128 = 16 -> conflict-free

// ---- SMEM byte offsets ----
#define XF_OFF     0                         // X A-frags fp16: 32KB
#define HS_OFF     32768                     // Hs fp16: 64*264*2 = 33792
#define B1_OFF     66560                     // fp32 bias1: 4KB
#define B2_OFF     70656                     // fp32 bias2: 1KB
#define SMEM_TOTAL 71680

// Pre-masked fp16 weights in m16n8k16 fragment-pair layout (see prep_weights). 512KB each.
__device__ __half g_w1h[D_HIDDEN * D_MODEL];
__device__ __half g_w2h[D_HIDDEN * D_MODEL];

// ======================= helpers =======================
__device__ __forceinline__ void mma_h(float c[4],
                                      uint32_t a0, uint32_t a1, uint32_t a2, uint32_t a3,
                                      uint32_t b0, uint32_t b1) {
    asm volatile(
        "mma.sync.aligned.m16n8k16.row.col.f32.f16.f16.f32 "
        "{%0,%1,%2,%3}, {%4,%5,%6,%7}, {%8,%9}, {%0,%1,%2,%3};\n"
        : "+f"(c[0]), "+f"(c[1]), "+f"(c[2]), "+f"(c[3])
        : "r"(a0), "r"(a1), "r"(a2), "r"(a3), "r"(b0), "r"(b1));
}
__device__ __forceinline__ uint32_t pack_h2(float x, float y) {
    __half2 h = __floats2half2_rn(x, y);
    return *reinterpret_cast<uint32_t*>(&h);
}

// ============ weight prep: mask + fp16 round + k16 fragment-pair pack ============
// B frag (m16n8k16, col): thread (g = n&7, q = (k>>1)&3):
//   b0 = {B[2q][g], B[2q+1][g]} (k-lo), b1 = {B[2q+8][g], B[2q+9][g]} (k-hi)
// uint4 slot packs an (even, odd) n8-tile pair: {ev.b0, ev.b1, od.b0, od.b1}.
__global__ void prep_weights(const float* __restrict__ w1,
                             const float* __restrict__ w2,
                             const int* __restrict__ mask) {
    int idx = blockIdx.x * blockDim.x + threadIdx.x;
    if (idx >= D_HIDDEN * D_MODEL) return;
    int h = idx >> 8;
    int d = idx & 255;
    float m = (mask[idx] != 0) ? 1.0f : 0.0f;

    // ---- W1: n = h (1024), k = d (256). jpg = h>>4 (64), kstep = d>>4 (16). ----
    {
        __half v = __float2half_rn(w1[idx] * m);
        int f4   = (((h >> 4) * 16) + (d >> 4)) * 32 + (h & 7) * 4 + ((d >> 1) & 3);
        int comp = ((h >> 3) & 1) * 2 + ((d & 15) >> 3);
        g_w1h[f4 * 8 + comp * 2 + (d & 1)] = v;
    }
    // ---- W2: n = d (256), k = h (1024). jpg = d>>4 (16), kstep = h>>4 (64). ----
    {
        __half v = __float2half_rn(w2[(size_t)d * D_HIDDEN + h] * m);
        int f4   = (((d >> 4) * 64) + (h >> 4)) * 32 + (d & 7) * 4 + ((h >> 1) & 3);
        int comp = ((d >> 3) & 1) * 2 + ((h & 15) >> 3);
        g_w2h[f4 * 8 + comp * 2 + (h & 1)] = v;
    }
}

// ======================= fused MLP (fp16 MMA, weights via LDG) =======================
__global__ __launch_bounds__(256, 1)
void ffd_h16(const float* __restrict__ x,
             const float* __restrict__ b1,
             const float* __restrict__ b2,
             float* __restrict__ out,
             int n_tokens) {
    extern __shared__ char smem[];
    __half* Hs  = (__half*)(smem + HS_OFF);
    float*  b1s = (float*)(smem + B1_OFF);
    float*  b2s = (float*)(smem + B2_OFF);

    const int tid   = threadIdx.x;
    const int warp  = tid >> 5;    // 0..7
    const int lane  = tid & 31;
    const int g     = lane >> 2;
    const int q     = lane & 3;
    const int hcoff = warp >> 2;   // 0..1: 128-hidden block within 256-pass
    const int wq4   = warp & 3;    // 0..3: 32-col stripe within the 128 block
    const int mt    = blockIdx.x * TM;

    // ---- X tile -> fp16 A-fragment layout ----
    // A frag (m16k16, row): thread (g,q): a0={A[g][2q],A[g][2q+1]}, a1=rows+8,
    // a2={A[g][2q+8],A[g][2q+9]}, a3=rows+8 k-hi. uint4 comps = {a0,a1,a2,a3}.
    #pragma unroll
    for (int i = 0; i < 16; i++) {
        int lin = tid + i * 256;          // 4096 float4 of x
        int row = lin >> 6, c4 = lin & 63;
        int tok = mt + row;
        float4 v = make_float4(0.f, 0.f, 0.f, 0.f);
        if (tok < n_tokens)
            v = *reinterpret_cast<const float4*>(x + (size_t)tok * D_MODEL + c4 * 4);
        int m     = row >> 4, gg = row & 7, rh = (row >> 3) & 1;
        int kstep = c4 >> 2;
        int reg   = (c4 >> 1) & 1;
        int comp  = reg * 2 + rh;
        int q0    = (c4 & 1) * 2;
        int f4    = (m * 16 + kstep) * 32 + gg * 4 + q0;
        *(uint32_t*)(smem + XF_OFF + f4 * 16 + comp * 4)        = pack_h2(v.x, v.y);
        *(uint32_t*)(smem + XF_OFF + (f4 + 1) * 16 + comp * 4)  = pack_h2(v.z, v.w);
    }
    #pragma unroll
    for (int i = tid; i < D_HIDDEN; i += 256) b1s[i] = b1[i];
    b2s[tid] = b2[tid];
    __syncthreads();

    float yacc[4][2][2][4];
    #pragma unroll
    for (int m = 0; m < 4; m++)
        #pragma unroll
        for (int jp = 0; jp < 2; jp++)
            #pragma unroll
            for (int pr = 0; pr < 2; pr++)
                #pragma unroll
                for (int r = 0; r < 4; r++) yacc[m][jp][pr][r] = 0.f;

    const uint4* XsF4 = (const uint4*)(smem + XF_OFF);
    const uint4* W1f  = (const uint4*)g_w1h;
    const uint4* W2f  = (const uint4*)g_w2h;

    for (int p = 0; p < 4; p++) {          // 4 passes over 256 hidden units
        float hacc[4][2][2][4];
        #pragma unroll
        for (int m = 0; m < 4; m++)
            #pragma unroll
            for (int jp = 0; jp < 2; jp++)
                #pragma unroll
                for (int pr = 0; pr < 2; pr++)
                    #pragma unroll
                    for (int r = 0; r < 4; r++) hacc[m][jp][pr][r] = 0.f;

        // ======== GEMM1: H[64,256] = X[64,256] @ W1p^T ========
        // warp: 64 rows x hidden cols [hcoff*128 + wq4*32, +32)  (jpg pair jb, jb+1)
        const int jb = p * 16 + hcoff * 8 + wq4 * 2;
        #pragma unroll
        for (int ks = 0; ks < 16; ks++) {
            uint4 B0 = __ldg(W1f + ((jb + 0) * 16 + ks) * 32 + lane);
            uint4 B1 = __ldg(W1f + ((jb + 1) * 16 + ks) * 32 + lane);
            #pragma unroll
            for (int m = 0; m < 4; m++) {
                uint4 A = XsF4[(m * 16 + ks) * 32 + lane];
                mma_h(hacc[m][0][0], A.x, A.y, A.z, A.w, B0.x, B0.y);
                mma_h(hacc[m][0][1], A.x, A.y, A.z, A.w, B0.z, B0.w);
                mma_h(hacc[m][1][0], A.x, A.y, A.z, A.w, B1.x, B1.y);
                mma_h(hacc[m][1][1], A.x, A.y, A.z, A.w, B1.z, B1.w);
            }
        }

        __syncthreads();   // previous pass GEMM2 finished reading Hs

        // ---- bias + relu -> Hs (fp16 row-major) ----
        #pragma unroll
        for (int m = 0; m < 4; m++) {
            int r0 = m * 16 + g;
            #pragma unroll
            for (int jp = 0; jp < 2; jp++) {
                #pragma unroll
                for (int pr = 0; pr < 2; pr++) {
                    int hl  = hcoff * 128 + wq4 * 32 + jp * 16 + pr * 8 + 2 * q;
                    float bb0 = b1s[p * 256 + hl];
                    float bb1 = b1s[p * 256 + hl + 1];
                    float* c = hacc[m][jp][pr];
                    *(uint32_t*)&Hs[r0 * HS2h + hl] =
                        pack_h2(fmaxf(c[0] + bb0, 0.f), fmaxf(c[1] + bb1, 0.f));
                    *(uint32_t*)&Hs[(r0 + 8) * HS2h + hl] =
                        pack_h2(fmaxf(c[2] + bb0, 0.f), fmaxf(c[3] + bb1, 0.f));
                }
            }
        }
        __syncthreads();

        // ======== GEMM2: Y[64,256] += relu(H)[64,256] @ W2p ========
        // warp: 64 rows x out cols [warp*32, +32)  (jpg2 pair jb2, jb2+1)
        const int jb2 = warp * 2;
        #pragma unroll
        for (int ks = 0; ks < 16; ks++) {
            const int ksg = p * 16 + ks;
            uint4 B0 = __ldg(W2f + ((jb2 + 0) * 64 + ksg) * 32 + lane);
            uint4 B1 = __ldg(W2f + ((jb2 + 1) * 64 + ksg) * 32 + lane);
            #pragma unroll
            for (int m = 0; m < 4; m++) {
                int r0 = m * 16 + g;
                const __half* hp = Hs + r0 * HS2h + ks * 16 + 2 * q;
                uint32_t a0 = *(const uint32_t*)hp;
                uint32_t a1 = *(const uint32_t*)(hp + 8 * HS2h);
                uint32_t a2 = *(const uint32_t*)(hp + 8);
                uint32_t a3 = *(const uint32_t*)(hp + 8 * HS2h + 8);
                mma_h(yacc[m][0][0], a0, a1, a2, a3, B0.x, B0.y);
                mma_h(yacc[m][0][1], a0, a1, a2, a3, B0.z, B0.w);
                mma_h(yacc[m][1][0], a0, a1, a2, a3, B1.x, B1.y);
                mma_h(yacc[m][1][1], a0, a1, a2, a3, B1.z, B1.w);
            }
        }
    }

    // ---- epilogue: + b2, write out ----
    #pragma unroll
    for (int m = 0; m < 4; m++) {
        int r0 = m * 16 + g;
        int tok0 = mt + r0;
        int tok1 = tok0 + 8;
        #pragma unroll
        for (int jp = 0; jp < 2; jp++) {
            #pragma unroll
            for (int pr = 0; pr < 2; pr++) {
                int d = warp * 32 + jp * 16 + pr * 8 + 2 * q;
                float bb0 = b2s[d];
                float bb1 = b2s[d + 1];
                float* c = yacc[m][jp][pr];
                if (tok0 < n_tokens) {
                    float2 v = make_float2(c[0] + bb0, c[1] + bb1);
                    *reinterpret_cast<float2*>(out + (size_t)tok0 * D_MODEL + d) = v;
                }
                if (tok1 < n_tokens) {
                    float2 v = make_float2(c[2] + bb0, c[3] + bb1);
                    *reinterpret_cast<float2*>(out + (size_t)tok1 * D_MODEL + d) = v;
                }
            }
        }
    }
}

extern "C" void kernel_launch(void* const* d_in, const int* in_sizes, int n_in,
                              void* d_out, int out_size) {
    // inputs (metadata order): x, w1, b1, w2, b2, mask
    const float* x    = (const float*)d_in[0];
    const float* w1   = (const float*)d_in[1];
    const float* b1   = (const float*)d_in[2];
    const float* w2   = (const float*)d_in[3];
    const float* b2   = (const float*)d_in[4];
    const int*   mask = (const int*)d_in[5];
    float* out = (float*)d_out;

    const int n_tokens = in_sizes[0] / D_MODEL;

    prep_weights<<<(D_HIDDEN * D_MODEL + 255) / 256, 256>>>(w1, w2, mask);

    cudaFuncSetAttribute(ffd_h16, cudaFuncAttributeMaxDynamicSharedMemorySize, SMEM_TOTAL);
    const int grid = (n_tokens + TM - 1) / TM;
    ffd_h16<<<grid, 256, SMEM_TOTAL>>>(x, b1, b2, out, n_tokens);
}

// round 14
// speedup vs baseline: 2.4948x; 1.0484x over previous
#include <cuda_runtime.h>
#include <cuda_fp16.h>
#include <cstdint>

#define D_MODEL  256
#define D_HIDDEN 1024
#define TM       64          // tokens per CTA
#define HS2h     264         // Hs row stride in halves: 528B stride -> conflict-free frag loads

// ---- SMEM byte offsets ----
#define XF_OFF     0                         // X A-frags fp16: 32KB
#define HS_OFF     32768                     // Hs fp16 double buffer: 2 x 33792
#define HS_BUF     33792
#define B1_OFF     (HS_OFF + 2 * HS_BUF)     // fp32 bias1: 4KB
#define B2_OFF     (B1_OFF + 4096)           // fp32 bias2: 1KB
#define SMEM_TOTAL (B2_OFF + 1024)           // 105472

// Pre-masked fp16 weights in m16n8k16 fragment-pair layout (see prep_weights). 512KB each.
__device__ __half g_w1h[D_HIDDEN * D_MODEL];
__device__ __half g_w2h[D_HIDDEN * D_MODEL];

// ======================= helpers =======================
__device__ __forceinline__ void mma_h(float c[4],
                                      uint32_t a0, uint32_t a1, uint32_t a2, uint32_t a3,
                                      uint32_t b0, uint32_t b1) {
    asm volatile(
        "mma.sync.aligned.m16n8k16.row.col.f32.f16.f16.f32 "
        "{%0,%1,%2,%3}, {%4,%5,%6,%7}, {%8,%9}, {%0,%1,%2,%3};\n"
        : "+f"(c[0]), "+f"(c[1]), "+f"(c[2]), "+f"(c[3])
        : "r"(a0), "r"(a1), "r"(a2), "r"(a3), "r"(b0), "r"(b1));
}
__device__ __forceinline__ uint32_t pack_h2(float x, float y) {
    __half2 h = __floats2half2_rn(x, y);
    return *reinterpret_cast<uint32_t*>(&h);
}

// ============ weight prep: mask + fp16 round + k16 fragment-pair pack ============
// (unchanged from passing R13 kernel — layout verified)
__global__ void prep_weights(const float* __restrict__ w1,
                             const float* __restrict__ w2,
                             const int* __restrict__ mask) {
    int idx = blockIdx.x * blockDim.x + threadIdx.x;
    if (idx >= D_HIDDEN * D_MODEL) return;
    int h = idx >> 8;
    int d = idx & 255;
    float m = (mask[idx] != 0) ? 1.0f : 0.0f;

    // ---- W1: n = h (1024), k = d (256). jpg = h>>4 (64), kstep = d>>4 (16). ----
    {
        __half v = __float2half_rn(w1[idx] * m);
        int f4   = (((h >> 4) * 16) + (d >> 4)) * 32 + (h & 7) * 4 + ((d >> 1) & 3);
        int comp = ((h >> 3) & 1) * 2 + ((d & 15) >> 3);
        g_w1h[f4 * 8 + comp * 2 + (d & 1)] = v;
    }
    // ---- W2: n = d (256), k = h (1024). jpg = d>>4 (16), kstep = h>>4 (64). ----
    {
        __half v = __float2half_rn(w2[(size_t)d * D_HIDDEN + h] * m);
        int f4   = (((d >> 4) * 64) + (h >> 4)) * 32 + (d & 7) * 4 + ((h >> 1) & 3);
        int comp = ((d >> 3) & 1) * 2 + ((h & 15) >> 3);
        g_w2h[f4 * 8 + comp * 2 + (h & 1)] = v;
    }
}

// ======================= fused MLP (fp16 MMA, pipelined operand fetch) =======================
__global__ __launch_bounds__(256, 1)
void ffd_h16(const float* __restrict__ x,
             const float* __restrict__ b1,
             const float* __restrict__ b2,
             float* __restrict__ out,
             int n_tokens) {
    extern __shared__ char smem[];
    float* b1s = (float*)(smem + B1_OFF);
    float* b2s = (float*)(smem + B2_OFF);

    const int tid   = threadIdx.x;
    const int warp  = tid >> 5;    // 0..7
    const int lane  = tid & 31;
    const int g     = lane >> 2;
    const int q     = lane & 3;
    const int hcoff = warp >> 2;   // 0..1: 128-hidden block within 256-pass
    const int wq4   = warp & 3;    // 0..3: 32-col stripe within the 128 block
    const int mt    = blockIdx.x * TM;

    // ---- X tile -> fp16 A-fragment layout (verified R13) ----
    #pragma unroll
    for (int i = 0; i < 16; i++) {
        int lin = tid + i * 256;          // 4096 float4 of x
        int row = lin >> 6, c4 = lin & 63;
        int tok = mt + row;
        float4 v = make_float4(0.f, 0.f, 0.f, 0.f);
        if (tok < n_tokens)
            v = *reinterpret_cast<const float4*>(x + (size_t)tok * D_MODEL + c4 * 4);
        int m     = row >> 4, gg = row & 7, rh = (row >> 3) & 1;
        int kstep = c4 >> 2;
        int reg   = (c4 >> 1) & 1;
        int comp  = reg * 2 + rh;
        int q0    = (c4 & 1) * 2;
        int f4    = (m * 16 + kstep) * 32 + gg * 4 + q0;
        *(uint32_t*)(smem + XF_OFF + f4 * 16 + comp * 4)        = pack_h2(v.x, v.y);
        *(uint32_t*)(smem + XF_OFF + (f4 + 1) * 16 + comp * 4)  = pack_h2(v.z, v.w);
    }
    #pragma unroll
    for (int i = tid; i < D_HIDDEN; i += 256) b1s[i] = b1[i];
    b2s[tid] = b2[tid];
    __syncthreads();

    float yacc[4][2][2][4];
    #pragma unroll
    for (int m = 0; m < 4; m++)
        #pragma unroll
        for (int jp = 0; jp < 2; jp++)
            #pragma unroll
            for (int pr = 0; pr < 2; pr++)
                #pragma unroll
                for (int r = 0; r < 4; r++) yacc[m][jp][pr][r] = 0.f;

    const uint4* XsF4 = (const uint4*)(smem + XF_OFF);
    const uint4* W1f  = (const uint4*)g_w1h;
    const uint4* W2f  = (const uint4*)g_w2h;

    for (int p = 0; p < 4; p++) {          // 4 passes over 256 hidden units
        __half* Hs = (__half*)(smem + HS_OFF + (p & 1) * HS_BUF);

        float hacc[4][2][2][4];
        #pragma unroll
        for (int m = 0; m < 4; m++)
            #pragma unroll
            for (int jp = 0; jp < 2; jp++)
                #pragma unroll
                for (int pr = 0; pr < 2; pr++)
                    #pragma unroll
                    for (int r = 0; r < 4; r++) hacc[m][jp][pr][r] = 0.f;

        // ======== GEMM1: H[64,256] = X[64,256] @ W1p^T ========
        // warp: 64 rows x hidden cols [hcoff*128 + wq4*32, +32)
        {
            const int jb = p * 16 + hcoff * 8 + wq4 * 2;
            const uint4* pW = W1f + (size_t)(jb * 16) * 32 + lane;   // +512 for jb+1

            // software pipeline: B distance-2, A distance-1
            uint4 Bq0[2], Bq1[2];
            Bq0[0] = __ldg(pW);            Bq1[0] = __ldg(pW + 512);
            Bq0[1] = __ldg(pW + 32);       Bq1[1] = __ldg(pW + 544);
            uint4 Aq[4];
            #pragma unroll
            for (int m = 0; m < 4; m++) Aq[m] = XsF4[(m * 16) * 32 + lane];

            #pragma unroll
            for (int ks = 0; ks < 16; ks++) {
                uint4 B0 = Bq0[ks & 1], B1 = Bq1[ks & 1];
                if (ks + 2 < 16) {
                    Bq0[ks & 1] = __ldg(pW + (ks + 2) * 32);
                    Bq1[ks & 1] = __ldg(pW + 512 + (ks + 2) * 32);
                }
                uint4 Ac[4];
                #pragma unroll
                for (int m = 0; m < 4; m++) {
                    Ac[m] = Aq[m];
                    if (ks + 1 < 16) Aq[m] = XsF4[(m * 16 + ks + 1) * 32 + lane];
                }
                #pragma unroll
                for (int m = 0; m < 4; m++) {
                    mma_h(hacc[m][0][0], Ac[m].x, Ac[m].y, Ac[m].z, Ac[m].w, B0.x, B0.y);
                    mma_h(hacc[m][0][1], Ac[m].x, Ac[m].y, Ac[m].z, Ac[m].w, B0.z, B0.w);
                    mma_h(hacc[m][1][0], Ac[m].x, Ac[m].y, Ac[m].z, Ac[m].w, B1.x, B1.y);
                    mma_h(hacc[m][1][1], Ac[m].x, Ac[m].y, Ac[m].z, Ac[m].w, B1.z, B1.w);
                }
            }
        }

        // ---- bias + relu -> Hs[p&1] (fp16 row-major) ----
        #pragma unroll
        for (int m = 0; m < 4; m++) {
            int r0 = m * 16 + g;
            #pragma unroll
            for (int jp = 0; jp < 2; jp++) {
                #pragma unroll
                for (int pr = 0; pr < 2; pr++) {
                    int hl  = hcoff * 128 + wq4 * 32 + jp * 16 + pr * 8 + 2 * q;
                    float bb0 = b1s[p * 256 + hl];
                    float bb1 = b1s[p * 256 + hl + 1];
                    float* c = hacc[m][jp][pr];
                    *(uint32_t*)&Hs[r0 * HS2h + hl] =
                        pack_h2(fmaxf(c[0] + bb0, 0.f), fmaxf(c[1] + bb1, 0.f));
                    *(uint32_t*)&Hs[(r0 + 8) * HS2h + hl] =
                        pack_h2(fmaxf(c[2] + bb0, 0.f), fmaxf(c[3] + bb1, 0.f));
                }
            }
        }
        __syncthreads();    // the ONLY barrier per pass (Hs double-buffered)

        // ======== GEMM2: Y[64,256] += relu(H)[64,256] @ W2p ========
        // warp: 64 rows x out cols [warp*32, +32)
        {
            const uint4* pW = W2f + (size_t)(warp * 2 * 64 + p * 16) * 32 + lane; // +2048 for jb2+1

            uint4 Bq0[2], Bq1[2];
            Bq0[0] = __ldg(pW);            Bq1[0] = __ldg(pW + 2048);
            Bq0[1] = __ldg(pW + 32);       Bq1[1] = __ldg(pW + 2080);

            #pragma unroll
            for (int ks = 0; ks < 16; ks++) {
                uint4 B0 = Bq0[ks & 1], B1 = Bq1[ks & 1];
                if (ks + 2 < 16) {
                    Bq0[ks & 1] = __ldg(pW + (ks + 2) * 32);
                    Bq1[ks & 1] = __ldg(pW + 2048 + (ks + 2) * 32);
                }
                #pragma unroll
                for (int m = 0; m < 4; m++) {
                    int r0 = m * 16 + g;
                    const __half* hp = Hs + r0 * HS2h + ks * 16 + 2 * q;
                    uint32_t a0 = *(const uint32_t*)hp;
                    uint32_t a1 = *(const uint32_t*)(hp + 8 * HS2h);
                    uint32_t a2 = *(const uint32_t*)(hp + 8);
                    uint32_t a3 = *(const uint32_t*)(hp + 8 * HS2h + 8);
                    mma_h(yacc[m][0][0], a0, a1, a2, a3, B0.x, B0.y);
                    mma_h(yacc[m][0][1], a0, a1, a2, a3, B0.z, B0.w);
                    mma_h(yacc[m][1][0], a0, a1, a2, a3, B1.x, B1.y);
                    mma_h(yacc[m][1][1], a0, a1, a2, a3, B1.z, B1.w);
                }
            }
        }
    }

    // ---- epilogue: + b2, write out ----
    #pragma unroll
    for (int m = 0; m < 4; m++) {
        int r0 = m * 16 + g;
        int tok0 = mt + r0;
        int tok1 = tok0 + 8;
        #pragma unroll
        for (int jp = 0; jp < 2; jp++) {
            #pragma unroll
            for (int pr = 0; pr < 2; pr++) {
                int d = warp * 32 + jp * 16 + pr * 8 + 2 * q;
                float bb0 = b2s[d];
                float bb1 = b2s[d + 1];
                float* c = yacc[m][jp][pr];
                if (tok0 < n_tokens) {
                    float2 v = make_float2(c[0] + bb0, c[1] + bb1);
                    *reinterpret_cast<float2*>(out + (size_t)tok0 * D_MODEL + d) = v;
                }
                if (tok1 < n_tokens) {
                    float2 v = make_float2(c[2] + bb0, c[3] + bb1);
                    *reinterpret_cast<float2*>(out + (size_t)tok1 * D_MODEL + d) = v;
                }
            }
        }
    }
}

extern "C" void kernel_launch(void* const* d_in, const int* in_sizes, int n_in,
                              void* d_out, int out_size) {
    // inputs (metadata order): x, w1, b1, w2, b2, mask
    const float* x    = (const float*)d_in[0];
    const float* w1   = (const float*)d_in[1];
    const float* b1   = (const float*)d_in[2];
    const float* w2   = (const float*)d_in[3];
    const float* b2   = (const float*)d_in[4];
    const int*   mask = (const int*)d_in[5];
    float* out = (float*)d_out;

    const int n_tokens = in_sizes[0] / D_MODEL;

    prep_weights<<<(D_HIDDEN * D_MODEL + 255) / 256, 256>>>(w1, w2, mask);

    cudaFuncSetAttribute(ffd_h16, cudaFuncAttributeMaxDynamicSharedMemorySize, SMEM_TOTAL);
    const int grid = (n_tokens + TM - 1) / TM;
    ffd_h16<<<grid, 256, SMEM_TOTAL>>>(x, b1, b2, out, n_tokens);
}

// round 15
// speedup vs baseline: 2.5937x; 1.0397x over previous
#include <cuda_runtime.h>
#include <cuda_fp16.h>
#include <cstdint>

#define D_MODEL  256
#define D_HIDDEN 1024
#define TM       64          // tokens per CTA

// ---- SMEM byte offsets ----
#define XF_OFF     0                         // X A-frags fp16: 32KB
#define HS_OFF     32768                     // HsF fragment-layout double buffer: 2 x 32KB
#define HS_BUF     32768
#define B1_OFF     (HS_OFF + 2 * HS_BUF)     // fp32 bias1: 4KB
#define B2_OFF     (B1_OFF + 4096)           // fp32 bias2: 1KB
#define SMEM_TOTAL (B2_OFF + 1024)           // 103424

// Pre-masked fp16 weights in m16n8k16 fragment-pair layout (see prep_weights). 512KB each.
__device__ __half g_w1h[D_HIDDEN * D_MODEL];
__device__ __half g_w2h[D_HIDDEN * D_MODEL];

// ======================= helpers =======================
__device__ __forceinline__ void mma_h(float c[4],
                                      uint32_t a0, uint32_t a1, uint32_t a2, uint32_t a3,
                                      uint32_t b0, uint32_t b1) {
    asm volatile(
        "mma.sync.aligned.m16n8k16.row.col.f32.f16.f16.f32 "
        "{%0,%1,%2,%3}, {%4,%5,%6,%7}, {%8,%9}, {%0,%1,%2,%3};\n"
        : "+f"(c[0]), "+f"(c[1]), "+f"(c[2]), "+f"(c[3])
        : "r"(a0), "r"(a1), "r"(a2), "r"(a3), "r"(b0), "r"(b1));
}
__device__ __forceinline__ uint32_t pack_h2(float x, float y) {
    __half2 h = __floats2half2_rn(x, y);
    return *reinterpret_cast<uint32_t*>(&h);
}

// ============ weight prep: mask + fp16 round + k16 fragment-pair pack ============
// (unchanged from passing R13/R14 kernels — layout verified)
__global__ void prep_weights(const float* __restrict__ w1,
                             const float* __restrict__ w2,
                             const int* __restrict__ mask) {
    int idx = blockIdx.x * blockDim.x + threadIdx.x;
    if (idx >= D_HIDDEN * D_MODEL) return;
    int h = idx >> 8;
    int d = idx & 255;
    float m = (mask[idx] != 0) ? 1.0f : 0.0f;

    // ---- W1: n = h (1024), k = d (256). jpg = h>>4 (64), kstep = d>>4 (16). ----
    {
        __half v = __float2half_rn(w1[idx] * m);
        int f4   = (((h >> 4) * 16) + (d >> 4)) * 32 + (h & 7) * 4 + ((d >> 1) & 3);
        int comp = ((h >> 3) & 1) * 2 + ((d & 15) >> 3);
        g_w1h[f4 * 8 + comp * 2 + (d & 1)] = v;
    }
    // ---- W2: n = d (256), k = h (1024). jpg = d>>4 (16), kstep = h>>4 (64). ----
    {
        __half v = __float2half_rn(w2[(size_t)d * D_HIDDEN + h] * m);
        int f4   = (((d >> 4) * 64) + (h >> 4)) * 32 + (d & 7) * 4 + ((h >> 1) & 3);
        int comp = ((d >> 3) & 1) * 2 + ((h & 15) >> 3);
        g_w2h[f4 * 8 + comp * 2 + (h & 1)] = v;
    }
}

// ======================= fused MLP: cross-GEMM interleaved pipeline =======================
__global__ __launch_bounds__(256, 1)
void ffd_h16(const float* __restrict__ x,
             const float* __restrict__ b1,
             const float* __restrict__ b2,
             float* __restrict__ out,
             int n_tokens) {
    extern __shared__ char smem[];
    float* b1s = (float*)(smem + B1_OFF);
    float* b2s = (float*)(smem + B2_OFF);

    const int tid   = threadIdx.x;
    const int warp  = tid >> 5;    // 0..7
    const int lane  = tid & 31;
    const int g     = lane >> 2;
    const int q     = lane & 3;
    const int hcoff = warp >> 2;   // 0..1: 128-hidden block within 256-pass
    const int wq4   = warp & 3;    // 0..3: 32-col stripe within the 128 block
    const int W     = hcoff * 128 + wq4 * 32;   // warp's hidden-col base within a pass
    const int mt    = blockIdx.x * TM;

    // ---- X tile -> fp16 A-fragment layout (verified R13/R14) ----
    #pragma unroll
    for (int i = 0; i < 16; i++) {
        int lin = tid + i * 256;          // 4096 float4 of x
        int row = lin >> 6, c4 = lin & 63;
        int tok = mt + row;
        float4 v = make_float4(0.f, 0.f, 0.f, 0.f);
        if (tok < n_tokens)
            v = *reinterpret_cast<const float4*>(x + (size_t)tok * D_MODEL + c4 * 4);
        int m     = row >> 4, gg = row & 7, rh = (row >> 3) & 1;
        int kstep = c4 >> 2;
        int reg   = (c4 >> 1) & 1;
        int comp  = reg * 2 + rh;
        int q0    = (c4 & 1) * 2;
        int f4    = (m * 16 + kstep) * 32 + gg * 4 + q0;
        *(uint32_t*)(smem + XF_OFF + f4 * 16 + comp * 4)        = pack_h2(v.x, v.y);
        *(uint32_t*)(smem + XF_OFF + (f4 + 1) * 16 + comp * 4)  = pack_h2(v.z, v.w);
    }
    #pragma unroll
    for (int i = tid; i < D_HIDDEN; i += 256) b1s[i] = b1[i];
    b2s[tid] = b2[tid];
    __syncthreads();

    float yacc[4][2][2][4];
    #pragma unroll
    for (int m = 0; m < 4; m++)
        #pragma unroll
        for (int jp = 0; jp < 2; jp++)
            #pragma unroll
            for (int pr = 0; pr < 2; pr++)
                #pragma unroll
                for (int r = 0; r < 4; r++) yacc[m][jp][pr][r] = 0.f;

    float hacc[4][2][2][4];

    const uint4* XsF4 = (const uint4*)(smem + XF_OFF);
    const uint4* W1f  = (const uint4*)g_w1h;
    const uint4* W2f  = (const uint4*)g_w2h;

    // ---- epilogue helper lambda: hacc -> HsF[buf] in fragment layout ----
    auto epilogue = [&](int p, uint4* HsCur) {
        #pragma unroll
        for (int m = 0; m < 4; m++) {
            #pragma unroll
            for (int jp = 0; jp < 2; jp++) {
                int colLo = p * 256 + W + jp * 16 + 2 * q;        // pr=0 cols
                float bb0  = b1s[colLo];
                float bb1  = b1s[colLo + 1];
                float bb0h = b1s[colLo + 8];
                float bb1h = b1s[colLo + 9];
                float* c0 = hacc[m][jp][0];
                float* c1 = hacc[m][jp][1];
                uint4 v;
                v.x = pack_h2(fmaxf(c0[0] + bb0,  0.f), fmaxf(c0[1] + bb1,  0.f));
                v.y = pack_h2(fmaxf(c0[2] + bb0,  0.f), fmaxf(c0[3] + bb1,  0.f));
                v.z = pack_h2(fmaxf(c1[0] + bb0h, 0.f), fmaxf(c1[1] + bb1h, 0.f));
                v.w = pack_h2(fmaxf(c1[2] + bb0h, 0.f), fmaxf(c1[3] + bb1h, 0.f));
                int ks = hcoff * 8 + wq4 * 2 + jp;                 // frag k-step within pass
                HsCur[(m * 16 + ks) * 32 + lane] = v;
            }
        }
    };

    // ================= head: GEMM1(0) alone =================
    {
        #pragma unroll
        for (int m = 0; m < 4; m++)
            #pragma unroll
            for (int jp = 0; jp < 2; jp++)
                #pragma unroll
                for (int pr = 0; pr < 2; pr++)
                    #pragma unroll
                    for (int r = 0; r < 4; r++) hacc[m][jp][pr][r] = 0.f;

        const int jb = hcoff * 8 + wq4 * 2;                        // p = 0
        const uint4* pW = W1f + (size_t)(jb * 16) * 32 + lane;
        uint4 Bq0[2], Bq1[2];
        Bq0[0] = __ldg(pW);        Bq1[0] = __ldg(pW + 512);
        Bq0[1] = __ldg(pW + 32);   Bq1[1] = __ldg(pW + 544);

        #pragma unroll
        for (int ks = 0; ks < 16; ks++) {
            uint4 B0 = Bq0[ks & 1], B1 = Bq1[ks & 1];
            if (ks + 2 < 16) {
                Bq0[ks & 1] = __ldg(pW + (ks + 2) * 32);
                Bq1[ks & 1] = __ldg(pW + 512 + (ks + 2) * 32);
            }
            #pragma unroll
            for (int m = 0; m < 4; m++) {
                uint4 A = XsF4[(m * 16 + ks) * 32 + lane];
                mma_h(hacc[m][0][0], A.x, A.y, A.z, A.w, B0.x, B0.y);
                mma_h(hacc[m][0][1], A.x, A.y, A.z, A.w, B0.z, B0.w);
                mma_h(hacc[m][1][0], A.x, A.y, A.z, A.w, B1.x, B1.y);
                mma_h(hacc[m][1][1], A.x, A.y, A.z, A.w, B1.z, B1.w);
            }
        }
        epilogue(0, (uint4*)(smem + HS_OFF));
    }
    __syncthreads();

    // ================= merged passes: GEMM1(p) + GEMM2(p-1) =================
    for (int p = 1; p < 4; p++) {
        const uint4* HsPrev = (const uint4*)(smem + HS_OFF + ((p - 1) & 1) * HS_BUF);
        uint4*       HsCur  = (uint4*)(smem + HS_OFF + (p & 1) * HS_BUF);

        #pragma unroll
        for (int m = 0; m < 4; m++)
            #pragma unroll
            for (int jp = 0; jp < 2; jp++)
                #pragma unroll
                for (int pr = 0; pr < 2; pr++)
                    #pragma unroll
                    for (int r = 0; r < 4; r++) hacc[m][jp][pr][r] = 0.f;

        const int jb = p * 16 + hcoff * 8 + wq4 * 2;
        const uint4* pW1 = W1f + (size_t)(jb * 16) * 32 + lane;
        const uint4* pW2 = W2f + (size_t)(warp * 2 * 64 + (p - 1) * 16) * 32 + lane;

        uint4 B1q0[2], B1q1[2], B2q0[2], B2q1[2];
        B1q0[0] = __ldg(pW1);       B1q1[0] = __ldg(pW1 + 512);
        B1q0[1] = __ldg(pW1 + 32);  B1q1[1] = __ldg(pW1 + 544);
        B2q0[0] = __ldg(pW2);       B2q1[0] = __ldg(pW2 + 2048);
        B2q0[1] = __ldg(pW2 + 32);  B2q1[1] = __ldg(pW2 + 2080);

        #pragma unroll
        for (int ks = 0; ks < 16; ks++) {
            uint4 B10 = B1q0[ks & 1], B11 = B1q1[ks & 1];
            uint4 B20 = B2q0[ks & 1], B21 = B2q1[ks & 1];
            if (ks + 2 < 16) {
                B1q0[ks & 1] = __ldg(pW1 + (ks + 2) * 32);
                B1q1[ks & 1] = __ldg(pW1 + 512 + (ks + 2) * 32);
                B2q0[ks & 1] = __ldg(pW2 + (ks + 2) * 32);
                B2q1[ks & 1] = __ldg(pW2 + 2048 + (ks + 2) * 32);
            }
            #pragma unroll
            for (int m = 0; m < 4; m++) {
                uint4 A  = XsF4[(m * 16 + ks) * 32 + lane];
                uint4 Ah = HsPrev[(m * 16 + ks) * 32 + lane];
                mma_h(hacc[m][0][0], A.x, A.y, A.z, A.w, B10.x, B10.y);
                mma_h(hacc[m][0][1], A.x, A.y, A.z, A.w, B10.z, B10.w);
                mma_h(hacc[m][1][0], A.x, A.y, A.z, A.w, B11.x, B11.y);
                mma_h(hacc[m][1][1], A.x, A.y, A.z, A.w, B11.z, B11.w);
                mma_h(yacc[m][0][0], Ah.x, Ah.y, Ah.z, Ah.w, B20.x, B20.y);
                mma_h(yacc[m][0][1], Ah.x, Ah.y, Ah.z, Ah.w, B20.z, B20.w);
                mma_h(yacc[m][1][0], Ah.x, Ah.y, Ah.z, Ah.w, B21.x, B21.y);
                mma_h(yacc[m][1][1], Ah.x, Ah.y, Ah.z, Ah.w, B21.z, B21.w);
            }
        }
        epilogue(p, HsCur);
        __syncthreads();
    }

    // ================= tail: GEMM2(3) alone =================
    {
        const uint4* HsPrev = (const uint4*)(smem + HS_OFF + (3 & 1) * HS_BUF);
        const uint4* pW2 = W2f + (size_t)(warp * 2 * 64 + 3 * 16) * 32 + lane;
        uint4 Bq0[2], Bq1[2];
        Bq0[0] = __ldg(pW2);       Bq1[0] = __ldg(pW2 + 2048);
        Bq0[1] = __ldg(pW2 + 32);  Bq1[1] = __ldg(pW2 + 2080);

        #pragma unroll
        for (int ks = 0; ks < 16; ks++) {
            uint4 B0 = Bq0[ks & 1], B1 = Bq1[ks & 1];
            if (ks + 2 < 16) {
                Bq0[ks & 1] = __ldg(pW2 + (ks + 2) * 32);
                Bq1[ks & 1] = __ldg(pW2 + 2048 + (ks + 2) * 32);
            }
            #pragma unroll
            for (int m = 0; m < 4; m++) {
                uint4 Ah = HsPrev[(m * 16 + ks) * 32 + lane];
                mma_h(yacc[m][0][0], Ah.x, Ah.y, Ah.z, Ah.w, B0.x, B0.y);
                mma_h(yacc[m][0][1], Ah.x, Ah.y, Ah.z, Ah.w, B0.z, B0.w);
                mma_h(yacc[m][1][0], Ah.x, Ah.y, Ah.z, Ah.w, B1.x, B1.y);
                mma_h(yacc[m][1][1], Ah.x, Ah.y, Ah.z, Ah.w, B1.z, B1.w);
            }
        }
    }

    // ---- epilogue: + b2, write out ----
    #pragma unroll
    for (int m = 0; m < 4; m++) {
        int r0 = m * 16 + g;
        int tok0 = mt + r0;
        int tok1 = tok0 + 8;
        #pragma unroll
        for (int jp = 0; jp < 2; jp++) {
            #pragma unroll
            for (int pr = 0; pr < 2; pr++) {
                int d = warp * 32 + jp * 16 + pr * 8 + 2 * q;
                float bb0 = b2s[d];
                float bb1 = b2s[d + 1];
                float* c = yacc[m][jp][pr];
                if (tok0 < n_tokens) {
                    float2 v = make_float2(c[0] + bb0, c[1] + bb1);
                    *reinterpret_cast<float2*>(out + (size_t)tok0 * D_MODEL + d) = v;
                }
                if (tok1 < n_tokens) {
                    float2 v = make_float2(c[2] + bb0, c[3] + bb1);
                    *reinterpret_cast<float2*>(out + (size_t)tok1 * D_MODEL + d) = v;
                }
            }
        }
    }
}

extern "C" void kernel_launch(void* const* d_in, const int* in_sizes, int n_in,
                              void* d_out, int out_size) {
    // inputs (metadata order): x, w1, b1, w2, b2, mask
    const float* x    = (const float*)d_in[0];
    const float* w1   = (const float*)d_in[1];
    const float* b1   = (const float*)d_in[2];
    const float* w2   = (const float*)d_in[3];
    const float* b2   = (const float*)d_in[4];
    const int*   mask = (const int*)d_in[5];
    float* out = (float*)d_out;

    const int n_tokens = in_sizes[0] / D_MODEL;

    prep_weights<<<(D_HIDDEN * D_MODEL + 255) / 256, 256>>>(w1, w2, mask);

    cudaFuncSetAttribute(ffd_h16, cudaFuncAttributeMaxDynamicSharedMemorySize, SMEM_TOTAL);
    const int grid = (n_tokens + TM - 1) / TM;
    ffd_h16<<<grid, 256, SMEM_TOTAL>>>(x, b1, b2, out, n_tokens);
}

// round 16
// speedup vs baseline: 2.6066x; 1.0050x over previous
#include <cuda_runtime.h>
#include <cuda_fp16.h>
#include <cstdint>

#define D_MODEL  256
#define D_HIDDEN 1024
#define TM       64          // tokens per CTA

// ---- SMEM byte offsets ----
#define XF_OFF     0                         // X A-frags fp16: 32KB
#define HS_OFF     32768                     // HsF fragment-layout double buffer: 2 x 32KB
#define HS_BUF     32768
#define B1_OFF     (HS_OFF + 2 * HS_BUF)     // fp32 bias1: 4KB
#define B2_OFF     (B1_OFF + 4096)           // fp32 bias2: 1KB
#define SMEM_TOTAL (B2_OFF + 1024)           // 103424

// Pre-masked fp16 weights in m16n8k16 fragment-pair layout (see prep_weights). 512KB each.
__device__ __half g_w1h[D_HIDDEN * D_MODEL];
__device__ __half g_w2h[D_HIDDEN * D_MODEL];

// ======================= helpers =======================
__device__ __forceinline__ void mma_h(float c[4],
                                      uint32_t a0, uint32_t a1, uint32_t a2, uint32_t a3,
                                      uint32_t b0, uint32_t b1) {
    asm volatile(
        "mma.sync.aligned.m16n8k16.row.col.f32.f16.f16.f32 "
        "{%0,%1,%2,%3}, {%4,%5,%6,%7}, {%8,%9}, {%0,%1,%2,%3};\n"
        : "+f"(c[0]), "+f"(c[1]), "+f"(c[2]), "+f"(c[3])
        : "r"(a0), "r"(a1), "r"(a2), "r"(a3), "r"(b0), "r"(b1));
}
__device__ __forceinline__ uint32_t pack_h2(float x, float y) {
    __half2 h = __floats2half2_rn(x, y);
    return *reinterpret_cast<uint32_t*>(&h);
}

// ============ weight prep: mask + fp16 round + k16 fragment-pair pack ============
// (unchanged from passing R13-R15 kernels — layout verified)
__global__ void prep_weights(const float* __restrict__ w1,
                             const float* __restrict__ w2,
                             const int* __restrict__ mask) {
    int idx = blockIdx.x * blockDim.x + threadIdx.x;
    if (idx >= D_HIDDEN * D_MODEL) return;
    int h = idx >> 8;
    int d = idx & 255;
    float m = (mask[idx] != 0) ? 1.0f : 0.0f;

    // ---- W1: n = h (1024), k = d (256). jpg = h>>4 (64), kstep = d>>4 (16). ----
    {
        __half v = __float2half_rn(w1[idx] * m);
        int f4   = (((h >> 4) * 16) + (d >> 4)) * 32 + (h & 7) * 4 + ((d >> 1) & 3);
        int comp = ((h >> 3) & 1) * 2 + ((d & 15) >> 3);
        g_w1h[f4 * 8 + comp * 2 + (d & 1)] = v;
    }
    // ---- W2: n = d (256), k = h (1024). jpg = d>>4 (16), kstep = h>>4 (64). ----
    {
        __half v = __float2half_rn(w2[(size_t)d * D_HIDDEN + h] * m);
        int f4   = (((d >> 4) * 64) + (h >> 4)) * 32 + (d & 7) * 4 + ((h >> 1) & 3);
        int comp = ((d >> 3) & 1) * 2 + ((h & 15) >> 3);
        g_w2h[f4 * 8 + comp * 2 + (h & 1)] = v;
    }
}

// ======================= fused MLP: cross-GEMM interleave + full operand pipeline =======================
__global__ __launch_bounds__(256, 1)
void ffd_h16(const float* __restrict__ x,
             const float* __restrict__ b1,
             const float* __restrict__ b2,
             float* __restrict__ out,
             int n_tokens) {
    extern __shared__ char smem[];
    float* b1s = (float*)(smem + B1_OFF);
    float* b2s = (float*)(smem + B2_OFF);

    const int tid   = threadIdx.x;
    const int warp  = tid >> 5;    // 0..7
    const int lane  = tid & 31;
    const int g     = lane >> 2;
    const int q     = lane & 3;
    const int hcoff = warp >> 2;   // 0..1: 128-hidden block within 256-pass
    const int wq4   = warp & 3;    // 0..3: 32-col stripe within the 128 block
    const int W     = hcoff * 128 + wq4 * 32;   // warp's hidden-col base within a pass
    const int mt    = blockIdx.x * TM;

    // ---- X tile -> fp16 A-fragment layout (verified R13-R15) ----
    #pragma unroll
    for (int i = 0; i < 16; i++) {
        int lin = tid + i * 256;          // 4096 float4 of x
        int row = lin >> 6, c4 = lin & 63;
        int tok = mt + row;
        float4 v = make_float4(0.f, 0.f, 0.f, 0.f);
        if (tok < n_tokens)
            v = *reinterpret_cast<const float4*>(x + (size_t)tok * D_MODEL + c4 * 4);
        int m     = row >> 4, gg = row & 7, rh = (row >> 3) & 1;
        int kstep = c4 >> 2;
        int reg   = (c4 >> 1) & 1;
        int comp  = reg * 2 + rh;
        int q0    = (c4 & 1) * 2;
        int f4    = (m * 16 + kstep) * 32 + gg * 4 + q0;
        *(uint32_t*)(smem + XF_OFF + f4 * 16 + comp * 4)        = pack_h2(v.x, v.y);
        *(uint32_t*)(smem + XF_OFF + (f4 + 1) * 16 + comp * 4)  = pack_h2(v.z, v.w);
    }
    #pragma unroll
    for (int i = tid; i < D_HIDDEN; i += 256) b1s[i] = b1[i];
    b2s[tid] = b2[tid];
    __syncthreads();

    float yacc[4][2][2][4];
    #pragma unroll
    for (int m = 0; m < 4; m++)
        #pragma unroll
        for (int jp = 0; jp < 2; jp++)
            #pragma unroll
            for (int pr = 0; pr < 2; pr++)
                #pragma unroll
                for (int r = 0; r < 4; r++) yacc[m][jp][pr][r] = 0.f;

    float hacc[4][2][2][4];

    const uint4* XsF4 = (const uint4*)(smem + XF_OFF);
    const uint4* W1f  = (const uint4*)g_w1h;
    const uint4* W2f  = (const uint4*)g_w2h;

    // ---- epilogue helper: hacc -> HsF[buf] in fragment layout ----
    auto epilogue = [&](int p, uint4* HsCur) {
        #pragma unroll
        for (int m = 0; m < 4; m++) {
            #pragma unroll
            for (int jp = 0; jp < 2; jp++) {
                int colLo = p * 256 + W + jp * 16 + 2 * q;        // pr=0 cols
                float bb0  = b1s[colLo];
                float bb1  = b1s[colLo + 1];
                float bb0h = b1s[colLo + 8];
                float bb1h = b1s[colLo + 9];
                float* c0 = hacc[m][jp][0];
                float* c1 = hacc[m][jp][1];
                uint4 v;
                v.x = pack_h2(fmaxf(c0[0] + bb0,  0.f), fmaxf(c0[1] + bb1,  0.f));
                v.y = pack_h2(fmaxf(c0[2] + bb0,  0.f), fmaxf(c0[3] + bb1,  0.f));
                v.z = pack_h2(fmaxf(c1[0] + bb0h, 0.f), fmaxf(c1[1] + bb1h, 0.f));
                v.w = pack_h2(fmaxf(c1[2] + bb0h, 0.f), fmaxf(c1[3] + bb1h, 0.f));
                int ks = hcoff * 8 + wq4 * 2 + jp;                 // frag k-step within pass
                HsCur[(m * 16 + ks) * 32 + lane] = v;
            }
        }
    };

    // ================= head: GEMM1(0) alone (A dist-1, B dist-1) =================
    {
        #pragma unroll
        for (int m = 0; m < 4; m++)
            #pragma unroll
            for (int jp = 0; jp < 2; jp++)
                #pragma unroll
                for (int pr = 0; pr < 2; pr++)
                    #pragma unroll
                    for (int r = 0; r < 4; r++) hacc[m][jp][pr][r] = 0.f;

        const int jb = hcoff * 8 + wq4 * 2;                        // p = 0
        const uint4* pW = W1f + (size_t)(jb * 16) * 32 + lane;
        uint4 B0c = __ldg(pW);
        uint4 B1c = __ldg(pW + 512);
        uint4 Ac  = XsF4[lane];                                    // (m=0, ks=0)

        #pragma unroll
        for (int ks = 0; ks < 16; ks++) {
            uint4 B0n, B1n;
            if (ks < 15) {
                B0n = __ldg(pW + (ks + 1) * 32);
                B1n = __ldg(pW + 512 + (ks + 1) * 32);
            }
            #pragma unroll
            for (int m = 0; m < 4; m++) {
                uint4 An;
                if (m < 3)       An = XsF4[((m + 1) * 16 + ks) * 32 + lane];
                else if (ks < 15) An = XsF4[(ks + 1) * 32 + lane];
                mma_h(hacc[m][0][0], Ac.x, Ac.y, Ac.z, Ac.w, B0c.x, B0c.y);
                mma_h(hacc[m][0][1], Ac.x, Ac.y, Ac.z, Ac.w, B0c.z, B0c.w);
                mma_h(hacc[m][1][0], Ac.x, Ac.y, Ac.z, Ac.w, B1c.x, B1c.y);
                mma_h(hacc[m][1][1], Ac.x, Ac.y, Ac.z, Ac.w, B1c.z, B1c.w);
                Ac = An;
            }
            B0c = B0n; B1c = B1n;
        }
        epilogue(0, (uint4*)(smem + HS_OFF));
    }
    __syncthreads();

    // ================= merged passes: GEMM1(p) + GEMM2(p-1) =================
    for (int p = 1; p < 4; p++) {
        const uint4* HsPrev = (const uint4*)(smem + HS_OFF + ((p - 1) & 1) * HS_BUF);
        uint4*       HsCur  = (uint4*)(smem + HS_OFF + (p & 1) * HS_BUF);

        #pragma unroll
        for (int m = 0; m < 4; m++)
            #pragma unroll
            for (int jp = 0; jp < 2; jp++)
                #pragma unroll
                for (int pr = 0; pr < 2; pr++)
                    #pragma unroll
                    for (int r = 0; r < 4; r++) hacc[m][jp][pr][r] = 0.f;

        const int jb = p * 16 + hcoff * 8 + wq4 * 2;
        const uint4* pW1 = W1f + (size_t)(jb * 16) * 32 + lane;
        const uint4* pW2 = W2f + (size_t)(warp * 2 * 64 + (p - 1) * 16) * 32 + lane;

        uint4 B10 = __ldg(pW1);
        uint4 B11 = __ldg(pW1 + 512);
        uint4 B20 = __ldg(pW2);
        uint4 B21 = __ldg(pW2 + 2048);
        uint4 Ac  = XsF4[lane];
        uint4 Ahc = HsPrev[lane];

        #pragma unroll
        for (int ks = 0; ks < 16; ks++) {
            uint4 B10n, B11n, B20n, B21n;
            if (ks < 15) {
                B10n = __ldg(pW1 + (ks + 1) * 32);
                B11n = __ldg(pW1 + 512 + (ks + 1) * 32);
                B20n = __ldg(pW2 + (ks + 1) * 32);
                B21n = __ldg(pW2 + 2048 + (ks + 1) * 32);
            }
            #pragma unroll
            for (int m = 0; m < 4; m++) {
                uint4 An, Ahn;
                if (m < 3) {
                    An  = XsF4[((m + 1) * 16 + ks) * 32 + lane];
                    Ahn = HsPrev[((m + 1) * 16 + ks) * 32 + lane];
                } else if (ks < 15) {
                    An  = XsF4[(ks + 1) * 32 + lane];
                    Ahn = HsPrev[(ks + 1) * 32 + lane];
                }
                mma_h(hacc[m][0][0], Ac.x, Ac.y, Ac.z, Ac.w, B10.x, B10.y);
                mma_h(hacc[m][0][1], Ac.x, Ac.y, Ac.z, Ac.w, B10.z, B10.w);
                mma_h(hacc[m][1][0], Ac.x, Ac.y, Ac.z, Ac.w, B11.x, B11.y);
                mma_h(hacc[m][1][1], Ac.x, Ac.y, Ac.z, Ac.w, B11.z, B11.w);
                mma_h(yacc[m][0][0], Ahc.x, Ahc.y, Ahc.z, Ahc.w, B20.x, B20.y);
                mma_h(yacc[m][0][1], Ahc.x, Ahc.y, Ahc.z, Ahc.w, B20.z, B20.w);
                mma_h(yacc[m][1][0], Ahc.x, Ahc.y, Ahc.z, Ahc.w, B21.x, B21.y);
                mma_h(yacc[m][1][1], Ahc.x, Ahc.y, Ahc.z, Ahc.w, B21.z, B21.w);
                Ac = An; Ahc = Ahn;
            }
            B10 = B10n; B11 = B11n; B20 = B20n; B21 = B21n;
        }
        epilogue(p, HsCur);
        __syncthreads();
    }

    // ================= tail: GEMM2(3) alone (Ah dist-1, B dist-1) =================
    {
        const uint4* HsPrev = (const uint4*)(smem + HS_OFF + (3 & 1) * HS_BUF);
        const uint4* pW2 = W2f + (size_t)(warp * 2 * 64 + 3 * 16) * 32 + lane;
        uint4 B0c = __ldg(pW2);
        uint4 B1c = __ldg(pW2 + 2048);
        uint4 Ahc = HsPrev[lane];

        #pragma unroll
        for (int ks = 0; ks < 16; ks++) {
            uint4 B0n, B1n;
            if (ks < 15) {
                B0n = __ldg(pW2 + (ks + 1) * 32);
                B1n = __ldg(pW2 + 2048 + (ks + 1) * 32);
            }
            #pragma unroll
            for (int m = 0; m < 4; m++) {
                uint4 Ahn;
                if (m < 3)        Ahn = HsPrev[((m + 1) * 16 + ks) * 32 + lane];
                else if (ks < 15) Ahn = HsPrev[(ks + 1) * 32 + lane];
                mma_h(yacc[m][0][0], Ahc.x, Ahc.y, Ahc.z, Ahc.w, B0c.x, B0c.y);
                mma_h(yacc[m][0][1], Ahc.x, Ahc.y, Ahc.z, Ahc.w, B0c.z, B0c.w);
                mma_h(yacc[m][1][0], Ahc.x, Ahc.y, Ahc.z, Ahc.w, B1c.x, B1c.y);
                mma_h(yacc[m][1][1], Ahc.x, Ahc.y, Ahc.z, Ahc.w, B1c.z, B1c.w);
                Ahc = Ahn;
            }
            B0c = B0n; B1c = B1n;
        }
    }

    // ---- epilogue: + b2, write out ----
    #pragma unroll
    for (int m = 0; m < 4; m++) {
        int r0 = m * 16 + g;
        int tok0 = mt + r0;
        int tok1 = tok0 + 8;
        #pragma unroll
        for (int jp = 0; jp < 2; jp++) {
            #pragma unroll
            for (int pr = 0; pr < 2; pr++) {
                int d = warp * 32 + jp * 16 + pr * 8 + 2 * q;
                float bb0 = b2s[d];
                float bb1 = b2s[d + 1];
                float* c = yacc[m][jp][pr];
                if (tok0 < n_tokens) {
                    float2 v = make_float2(c[0] + bb0, c[1] + bb1);
                    *reinterpret_cast<float2*>(out + (size_t)tok0 * D_MODEL + d) = v;
                }
                if (tok1 < n_tokens) {
                    float2 v = make_float2(c[2] + bb0, c[3] + bb1);
                    *reinterpret_cast<float2*>(out + (size_t)tok1 * D_MODEL + d) = v;
                }
            }
        }
    }
}

extern "C" void kernel_launch(void* const* d_in, const int* in_sizes, int n_in,
                              void* d_out, int out_size) {
    // inputs (metadata order): x, w1, b1, w2, b2, mask
    const float* x    = (const float*)d_in[0];
    const float* w1   = (const float*)d_in[1];
    const float* b1   = (const float*)d_in[2];
    const float* w2   = (const float*)d_in[3];
    const float* b2   = (const float*)d_in[4];
    const int*   mask = (const int*)d_in[5];
    float* out = (float*)d_out;

    const int n_tokens = in_sizes[0] / D_MODEL;

    prep_weights<<<(D_HIDDEN * D_MODEL + 255) / 256, 256>>>(w1, w2, mask);

    cudaFuncSetAttribute(ffd_h16, cudaFuncAttributeMaxDynamicSharedMemorySize, SMEM_TOTAL);
    const int grid = (n_tokens + TM - 1) / TM;
    ffd_h16<<<grid, 256, SMEM_TOTAL>>>(x, b1, b2, out, n_tokens);
}